// round 2
// baseline (speedup 1.0000x reference)
#include <cuda_runtime.h>
#include <math.h>

// Problem constants
#define B_N 4
#define S_N 2048
#define D_N 1024
#define H_N 16
#define DK_N 64
#define M_N (B_N * S_N)   // 8192 rows
#define LDT 132           // padded smem stride (floats)

// Scratch (allocation-free: static device globals)
__device__ float g_Q[(size_t)B_N * H_N * S_N * DK_N];
__device__ float g_K[(size_t)B_N * H_N * S_N * DK_N];
__device__ float g_V[(size_t)B_N * H_N * S_N * DK_N];
__device__ float g_C[(size_t)M_N * D_N];

// ---------------------------------------------------------------------------
// GEMM: out = A[M,1024] @ W[1024,1024]^T + bias  (nn.Linear semantics)
// Block tile 128x128, K-tile 16, 256 threads, 8x8 micro-tile, double-buffered.
// SPLIT=true  -> write to [B,H,S,DK] layout (for attention)
// SPLIT=false -> write flat [row, n]
// ---------------------------------------------------------------------------
template <bool SPLIT>
__global__ __launch_bounds__(256)
void gemm_bias_kernel(const float* __restrict__ A, const float* __restrict__ W,
                      const float* __restrict__ bias, float* __restrict__ out)
{
    __shared__ float As[2][16 * LDT];
    __shared__ float Bs[2][16 * LDT];

    const int tid = threadIdx.x;
    const int tx = tid & 15;         // 0..15 -> n direction
    const int ty = tid >> 4;         // 0..15 -> m direction
    const int bm = blockIdx.y;       // 0..63
    const int bn = blockIdx.x;       // 0..7

    const float* Ag = A + (size_t)bm * 128 * 1024;
    const float* Wg = W + (size_t)bn * 128 * 1024;

    // loader mapping: 512 float4 per 128x16 tile, 2 per thread
    const int f0 = tid;
    const int f1 = tid + 256;
    const int r0 = f0 >> 2, c0 = (f0 & 3) * 4;
    const int r1 = f1 >> 2, c1 = (f1 & 3) * 4;

    float4 a0, a1, b0, b1;

    // prologue: tile 0
    a0 = *(const float4*)(Ag + (size_t)r0 * 1024 + c0);
    a1 = *(const float4*)(Ag + (size_t)r1 * 1024 + c1);
    b0 = *(const float4*)(Wg + (size_t)r0 * 1024 + c0);
    b1 = *(const float4*)(Wg + (size_t)r1 * 1024 + c1);
    {
        int ba = c0 * LDT + r0;
        As[0][ba] = a0.x; As[0][ba + LDT] = a0.y; As[0][ba + 2*LDT] = a0.z; As[0][ba + 3*LDT] = a0.w;
        int bb = c1 * LDT + r1;
        As[0][bb] = a1.x; As[0][bb + LDT] = a1.y; As[0][bb + 2*LDT] = a1.z; As[0][bb + 3*LDT] = a1.w;
        Bs[0][ba] = b0.x; Bs[0][ba + LDT] = b0.y; Bs[0][ba + 2*LDT] = b0.z; Bs[0][ba + 3*LDT] = b0.w;
        Bs[0][bb] = b1.x; Bs[0][bb + LDT] = b1.y; Bs[0][bb + 2*LDT] = b1.z; Bs[0][bb + 3*LDT] = b1.w;
    }
    __syncthreads();

    float acc[8][8];
    #pragma unroll
    for (int i = 0; i < 8; ++i)
        #pragma unroll
        for (int j = 0; j < 8; ++j) acc[i][j] = 0.0f;

    for (int kt = 0; kt < 64; ++kt) {
        const int cur = kt & 1;
        if (kt + 1 < 64) {  // prefetch next tile into registers
            const float* Ap = Ag + (size_t)(kt + 1) * 16;
            const float* Wp = Wg + (size_t)(kt + 1) * 16;
            a0 = *(const float4*)(Ap + (size_t)r0 * 1024 + c0);
            a1 = *(const float4*)(Ap + (size_t)r1 * 1024 + c1);
            b0 = *(const float4*)(Wp + (size_t)r0 * 1024 + c0);
            b1 = *(const float4*)(Wp + (size_t)r1 * 1024 + c1);
        }
        #pragma unroll 4
        for (int k = 0; k < 16; ++k) {
            const float4 x0 = *(const float4*)&As[cur][k * LDT + ty * 8];
            const float4 x1 = *(const float4*)&As[cur][k * LDT + ty * 8 + 4];
            const float4 y0 = *(const float4*)&Bs[cur][k * LDT + tx * 8];
            const float4 y1 = *(const float4*)&Bs[cur][k * LDT + tx * 8 + 4];
            const float av[8] = {x0.x, x0.y, x0.z, x0.w, x1.x, x1.y, x1.z, x1.w};
            const float bv[8] = {y0.x, y0.y, y0.z, y0.w, y1.x, y1.y, y1.z, y1.w};
            #pragma unroll
            for (int i = 0; i < 8; ++i)
                #pragma unroll
                for (int j = 0; j < 8; ++j)
                    acc[i][j] = fmaf(av[i], bv[j], acc[i][j]);
        }
        if (kt + 1 < 64) {
            const int nxt = cur ^ 1;
            int ba = c0 * LDT + r0;
            As[nxt][ba] = a0.x; As[nxt][ba + LDT] = a0.y; As[nxt][ba + 2*LDT] = a0.z; As[nxt][ba + 3*LDT] = a0.w;
            int bb = c1 * LDT + r1;
            As[nxt][bb] = a1.x; As[nxt][bb + LDT] = a1.y; As[nxt][bb + 2*LDT] = a1.z; As[nxt][bb + 3*LDT] = a1.w;
            Bs[nxt][ba] = b0.x; Bs[nxt][ba + LDT] = b0.y; Bs[nxt][ba + 2*LDT] = b0.z; Bs[nxt][ba + 3*LDT] = b0.w;
            Bs[nxt][bb] = b1.x; Bs[nxt][bb + LDT] = b1.y; Bs[nxt][bb + 2*LDT] = b1.z; Bs[nxt][bb + 3*LDT] = b1.w;
            __syncthreads();
        }
    }

    // epilogue
    const int row0 = bm * 128 + ty * 8;
    const int n0 = bn * 128 + tx * 8;
    float bb8[8];
    #pragma unroll
    for (int j = 0; j < 8; ++j) bb8[j] = bias[n0 + j];

    #pragma unroll
    for (int i = 0; i < 8; ++i) {
        const int row = row0 + i;
        float4 v0, v1;
        v0.x = acc[i][0] + bb8[0]; v0.y = acc[i][1] + bb8[1];
        v0.z = acc[i][2] + bb8[2]; v0.w = acc[i][3] + bb8[3];
        v1.x = acc[i][4] + bb8[4]; v1.y = acc[i][5] + bb8[5];
        v1.z = acc[i][6] + bb8[6]; v1.w = acc[i][7] + bb8[7];
        if (SPLIT) {
            // out[((b*H + h)*S + s)*DK + dk]
            const int b = row >> 11;        // row / S_N
            const int s = row & (S_N - 1);
            const int h = n0 >> 6;          // same h for all 8 cols (n0 % 64 <= 56)
            const int dk = n0 & 63;
            float* dst = out + (((size_t)(b * H_N + h) * S_N + s) * DK_N) + dk;
            *(float4*)dst = v0;
            *(float4*)(dst + 4) = v1;
        } else {
            float* dst = out + (size_t)row * 1024 + n0;
            *(float4*)dst = v0;
            *(float4*)(dst + 4) = v1;
        }
    }
}

// ---------------------------------------------------------------------------
// Flash attention (fp32, online softmax).
// Block: one (b,h), 128 query rows. 256 threads = 16x16 grid.
//   Scores micro-tile: 8 rows x 8 keys per thread.
//   Output micro-tile: 8 rows x 4 dk per thread.
// smem: Qs[64][LDT] (d-major, pre-scaled) | Ps[128][LDT] (Ks aliases 1st half)
//       | Vs[128][64] | ms[128]
// ---------------------------------------------------------------------------
#define FLASH_SMEM_FLOATS (64 * LDT + 128 * LDT + 128 * 64 + 128)
#define FLASH_SMEM_BYTES (FLASH_SMEM_FLOATS * 4)

__global__ __launch_bounds__(256)
void flash_attn_kernel(const float* __restrict__ Q, const float* __restrict__ K,
                       const float* __restrict__ V, const int* __restrict__ mask,
                       float* __restrict__ out)
{
    extern __shared__ float sm[];
    float* Qs = sm;                          // 64*LDT  [d][r], scaled by 1/8
    float* Ps = sm + 64 * LDT;               // 128*LDT [r][c]  (PV phase)
    float* Ks = Ps;                          // 64*LDT  [d][c]  (S phase, aliased)
    float* Vs = Ps + 128 * LDT;              // 128*64  [c][d]
    int*   ms = (int*)(Vs + 128 * 64);       // 128

    const int tid = threadIdx.x;
    const int tx = tid & 15;
    const int ty = tid >> 4;
    const int bh = blockIdx.y;               // b*H + h
    const int q0 = blockIdx.x * 128;
    const int b = bh >> 4;
    const int h = bh & 15;

    const float* Qg = Q + ((size_t)bh * S_N + q0) * DK_N;
    const float* Kg = K + (size_t)bh * S_N * DK_N;
    const float* Vg = V + (size_t)bh * S_N * DK_N;
    const int* mg = mask + b * S_N;

    // Load Q tile (pre-scaled), transposed to [d][r]
    #pragma unroll
    for (int it = 0; it < 8; ++it) {
        const int f = tid + it * 256;        // 0..2047 float4 ids
        const int r = f >> 4;
        const int c4 = (f & 15) * 4;
        const float4 v = *(const float4*)(Qg + (size_t)r * 64 + c4);
        const int ba = c4 * LDT + r;
        Qs[ba]           = v.x * 0.125f;
        Qs[ba + LDT]     = v.y * 0.125f;
        Qs[ba + 2 * LDT] = v.z * 0.125f;
        Qs[ba + 3 * LDT] = v.w * 0.125f;
    }

    float m8[8], l8[8], o[8][4];
    #pragma unroll
    for (int i = 0; i < 8; ++i) {
        m8[i] = -1e30f;
        l8[i] = 0.0f;
        o[i][0] = o[i][1] = o[i][2] = o[i][3] = 0.0f;
    }

    for (int kt = 0; kt < 16; ++kt) {
        __syncthreads();  // prior PV (reads Ps/Vs) done; also covers Q load on kt=0
        const float* Kt = Kg + (size_t)kt * 128 * 64;
        const float* Vt = Vg + (size_t)kt * 128 * 64;
        #pragma unroll
        for (int it = 0; it < 8; ++it) {
            const int f = tid + it * 256;
            const int r = f >> 4;
            const int c4 = (f & 15) * 4;
            const float4 kv = *(const float4*)(Kt + (size_t)r * 64 + c4);
            const int ba = c4 * LDT + r;
            Ks[ba] = kv.x; Ks[ba + LDT] = kv.y; Ks[ba + 2*LDT] = kv.z; Ks[ba + 3*LDT] = kv.w;
            const float4 vv = *(const float4*)(Vt + (size_t)r * 64 + c4);
            *(float4*)(Vs + r * 64 + c4) = vv;
        }
        if (tid < 128) ms[tid] = mg[kt * 128 + tid];
        __syncthreads();

        // S = (Q*scale) @ K^T   (8x8 per thread)
        float sacc[8][8];
        #pragma unroll
        for (int i = 0; i < 8; ++i)
            #pragma unroll
            for (int j = 0; j < 8; ++j) sacc[i][j] = 0.0f;

        #pragma unroll 4
        for (int d = 0; d < 64; ++d) {
            const float4 x0 = *(const float4*)&Qs[d * LDT + ty * 8];
            const float4 x1 = *(const float4*)&Qs[d * LDT + ty * 8 + 4];
            const float4 y0 = *(const float4*)&Ks[d * LDT + tx * 8];
            const float4 y1 = *(const float4*)&Ks[d * LDT + tx * 8 + 4];
            const float av[8] = {x0.x, x0.y, x0.z, x0.w, x1.x, x1.y, x1.z, x1.w};
            const float bv[8] = {y0.x, y0.y, y0.z, y0.w, y1.x, y1.y, y1.z, y1.w};
            #pragma unroll
            for (int i = 0; i < 8; ++i)
                #pragma unroll
                for (int j = 0; j < 8; ++j)
                    sacc[i][j] = fmaf(av[i], bv[j], sacc[i][j]);
        }

        // mask (reference: where(mask==0, -1e9) after scaling)
        int mk[8];
        #pragma unroll
        for (int j = 0; j < 8; ++j) mk[j] = ms[tx * 8 + j];
        #pragma unroll
        for (int i = 0; i < 8; ++i)
            #pragma unroll
            for (int j = 0; j < 8; ++j)
                if (mk[j] == 0) sacc[i][j] = -1e9f;

        // online softmax update (row stats shared across the 16 tx lanes)
        #pragma unroll
        for (int i = 0; i < 8; ++i) {
            float tm = sacc[i][0];
            #pragma unroll
            for (int j = 1; j < 8; ++j) tm = fmaxf(tm, sacc[i][j]);
            tm = fmaxf(tm, __shfl_xor_sync(0xffffffffu, tm, 1));
            tm = fmaxf(tm, __shfl_xor_sync(0xffffffffu, tm, 2));
            tm = fmaxf(tm, __shfl_xor_sync(0xffffffffu, tm, 4));
            tm = fmaxf(tm, __shfl_xor_sync(0xffffffffu, tm, 8));
            const float nm = fmaxf(m8[i], tm);
            const float corr = __expf(m8[i] - nm);
            float rs = 0.0f;
            #pragma unroll
            for (int j = 0; j < 8; ++j) {
                const float p = __expf(sacc[i][j] - nm);
                sacc[i][j] = p;
                rs += p;
            }
            rs += __shfl_xor_sync(0xffffffffu, rs, 1);
            rs += __shfl_xor_sync(0xffffffffu, rs, 2);
            rs += __shfl_xor_sync(0xffffffffu, rs, 4);
            rs += __shfl_xor_sync(0xffffffffu, rs, 8);
            l8[i] = l8[i] * corr + rs;
            m8[i] = nm;
            o[i][0] *= corr; o[i][1] *= corr; o[i][2] *= corr; o[i][3] *= corr;
        }

        __syncthreads();  // all reads of Ks done before Ps overwrites it
        #pragma unroll
        for (int i = 0; i < 8; ++i) {
            float4 p0, p1;
            p0.x = sacc[i][0]; p0.y = sacc[i][1]; p0.z = sacc[i][2]; p0.w = sacc[i][3];
            p1.x = sacc[i][4]; p1.y = sacc[i][5]; p1.z = sacc[i][6]; p1.w = sacc[i][7];
            *(float4*)&Ps[(ty * 8 + i) * LDT + tx * 8] = p0;
            *(float4*)&Ps[(ty * 8 + i) * LDT + tx * 8 + 4] = p1;
        }
        __syncthreads();

        // O += P @ V  (8 rows x 4 dk per thread)
        #pragma unroll 2
        for (int j = 0; j < 128; ++j) {
            const float4 vv = *(const float4*)&Vs[j * 64 + tx * 4];
            #pragma unroll
            for (int i = 0; i < 8; ++i) {
                const float p = Ps[(ty * 8 + i) * LDT + j];  // broadcast across tx
                o[i][0] = fmaf(p, vv.x, o[i][0]);
                o[i][1] = fmaf(p, vv.y, o[i][1]);
                o[i][2] = fmaf(p, vv.z, o[i][2]);
                o[i][3] = fmaf(p, vv.w, o[i][3]);
            }
        }
    }

    // epilogue: ctx flat [b*S+s][D] at column h*64 + dk
    #pragma unroll
    for (int i = 0; i < 8; ++i) {
        const float inv = 1.0f / l8[i];
        const int s = q0 + ty * 8 + i;
        float4 v;
        v.x = o[i][0] * inv; v.y = o[i][1] * inv;
        v.z = o[i][2] * inv; v.w = o[i][3] * inv;
        *(float4*)(out + ((size_t)b * S_N + s) * D_N + h * 64 + tx * 4) = v;
    }
}

// ---------------------------------------------------------------------------
extern "C" void kernel_launch(void* const* d_in, const int* in_sizes, int n_in,
                              void* d_out, int out_size)
{
    (void)in_sizes; (void)n_in; (void)out_size;
    const float* query = (const float*)d_in[0];
    const float* key   = (const float*)d_in[1];
    const float* value = (const float*)d_in[2];
    const int*   mask  = (const int*)d_in[3];
    const float* Wq = (const float*)d_in[4];
    const float* bq = (const float*)d_in[5];
    const float* Wk = (const float*)d_in[6];
    const float* bk = (const float*)d_in[7];
    const float* Wv = (const float*)d_in[8];
    const float* bv = (const float*)d_in[9];
    const float* Wo = (const float*)d_in[10];
    const float* bo = (const float*)d_in[11];
    float* out = (float*)d_out;

    void *pQ, *pK, *pV, *pC;
    cudaGetSymbolAddress(&pQ, g_Q);
    cudaGetSymbolAddress(&pK, g_K);
    cudaGetSymbolAddress(&pV, g_V);
    cudaGetSymbolAddress(&pC, g_C);

    cudaFuncSetAttribute(flash_attn_kernel,
                         cudaFuncAttributeMaxDynamicSharedMemorySize,
                         FLASH_SMEM_BYTES);

    const dim3 gemm_grid(8, 64);   // N tiles x M tiles
    const dim3 gemm_block(256);

    gemm_bias_kernel<true><<<gemm_grid, gemm_block>>>(query, Wq, bq, (float*)pQ);
    gemm_bias_kernel<true><<<gemm_grid, gemm_block>>>(key,   Wk, bk, (float*)pK);
    gemm_bias_kernel<true><<<gemm_grid, gemm_block>>>(value, Wv, bv, (float*)pV);

    const dim3 fa_grid(S_N / 128, B_N * H_N);  // 16 x 64
    flash_attn_kernel<<<fa_grid, 256, FLASH_SMEM_BYTES>>>(
        (const float*)pQ, (const float*)pK, (const float*)pV, mask, (float*)pC);

    gemm_bias_kernel<false><<<gemm_grid, gemm_block>>>((const float*)pC, Wo, bo, out);
}

// round 5
// speedup vs baseline: 2.6916x; 2.6916x over previous
#include <cuda_runtime.h>
#include <cuda_bf16.h>
#include <stdint.h>

// Problem constants
#define B_N 4
#define S_N 2048
#define D_N 1024
#define H_N 16
#define DK_N 64
#define M_N (B_N * S_N)   // 8192

// Scratch (allocation-free: static device globals)
__device__ float g_Q[(size_t)B_N * H_N * S_N * DK_N];
__device__ float g_K[(size_t)B_N * H_N * S_N * DK_N];
__device__ float g_V[(size_t)B_N * H_N * S_N * DK_N];
__device__ float g_C[(size_t)M_N * D_N];

// ===========================================================================
// Portable tensor-op helpers (compute_103-safe: ldmatrix + mma.sync only)
// ===========================================================================
__device__ __forceinline__ uint32_t smem_u32(const void* p) {
    uint32_t a;
    asm("{ .reg .u64 t; cvta.to.shared.u64 t, %1; cvt.u32.u64 %0, t; }"
        : "=r"(a) : "l"(p));
    return a;
}

__device__ __forceinline__ void ldsm_x4(uint32_t* r, uint32_t addr) {
    asm volatile("ldmatrix.sync.aligned.m8n8.x4.shared.b16 {%0,%1,%2,%3}, [%4];"
        : "=r"(r[0]), "=r"(r[1]), "=r"(r[2]), "=r"(r[3]) : "r"(addr));
}
__device__ __forceinline__ void ldsm_x2(uint32_t* r, uint32_t addr) {
    asm volatile("ldmatrix.sync.aligned.m8n8.x2.shared.b16 {%0,%1}, [%2];"
        : "=r"(r[0]), "=r"(r[1]) : "r"(addr));
}
__device__ __forceinline__ void ldsm_x2t(uint32_t* r, uint32_t addr) {
    asm volatile("ldmatrix.sync.aligned.m8n8.x2.trans.shared.b16 {%0,%1}, [%2];"
        : "=r"(r[0]), "=r"(r[1]) : "r"(addr));
}

// D += A*B  (m16n8k16, bf16 in, fp32 accum)
__device__ __forceinline__ void mma16816(float* d, const uint32_t* a, const uint32_t* b) {
    asm volatile(
        "mma.sync.aligned.m16n8k16.row.col.f32.bf16.bf16.f32 "
        "{%0,%1,%2,%3}, {%4,%5,%6,%7}, {%8,%9}, {%0,%1,%2,%3};"
        : "+f"(d[0]), "+f"(d[1]), "+f"(d[2]), "+f"(d[3])
        : "r"(a[0]), "r"(a[1]), "r"(a[2]), "r"(a[3]), "r"(b[0]), "r"(b[1]));
}

// pack (x,y) -> bf16x2 hi word + bf16x2 lo (residual) word
__device__ __forceinline__ void bf16split2(float x, float y, uint32_t& hi, uint32_t& lo) {
    union { __nv_bfloat162 b; uint32_t u; } h, l;
    h.b = __floats2bfloat162_rn(x, y);
    l.b = __floats2bfloat162_rn(x - __low2float(h.b), y - __high2float(h.b));
    hi = h.u; lo = l.u;
}

// ===========================================================================
// GEMM: out = A[M,1024] @ W[1024,1024]^T + bias  (nn.Linear)
// CTA 128x128, BK=32, 256 threads (8 warps: 4m x 2n, warp tile 32x64).
// bf16 hi/lo split: 3 mma per (hi,lo) operand pair, fp32 accumulate.
// smem per stage: Ah|Al|Bh|Bl, each 128 x 40(b16 stride, pad) = 10240 B.
// ===========================================================================
#define G_LD 40                 // b16 elements per smem row (32 data + 8 pad)
#define G_TILE 10240            // 128*40*2 bytes
#define G_AH 0
#define G_AL 10240
#define G_BH 20480
#define G_BL 30720
#define G_STAGE 40960
#define SMEM_GEMM (2 * G_STAGE) // 81920

template <bool SPLIT>
__device__ __forceinline__ void gemm_mma_body(
    const float* __restrict__ A, const float* __restrict__ W,
    const float* __restrict__ bias, float* __restrict__ out,
    int bm, int bn)
{
    extern __shared__ char smg[];
    const uint32_t sb = smem_u32(smg);
    const int tid = threadIdx.x;
    const int lane = tid & 31;
    const int w = tid >> 5;
    const int wm = w & 3;        // m warp: 0..3 -> rows wm*32
    const int wn = w >> 2;       // n warp: 0..1 -> cols wn*64

    const float* Ag = A + (size_t)bm * 128 * 1024;
    const float* Wg = W + (size_t)bn * 128 * 1024;

    // loader: 1024 float4 per 128x32 tile, 4 per thread per matrix
    int lr[4], lc[4];
    #pragma unroll
    for (int i = 0; i < 4; ++i) {
        const int f = tid + i * 256;
        lr[i] = f >> 3;
        lc[i] = (f & 7) * 4;
    }

    float4 pa[4], pb[4];
    // prologue: tile 0 -> smem stage 0
    #pragma unroll
    for (int i = 0; i < 4; ++i) {
        pa[i] = *(const float4*)(Ag + (size_t)lr[i] * 1024 + lc[i]);
        pb[i] = *(const float4*)(Wg + (size_t)lr[i] * 1024 + lc[i]);
    }
    #pragma unroll
    for (int i = 0; i < 4; ++i) {
        const int off = lr[i] * (G_LD * 2) + lc[i] * 2;
        uint32_t h0, l0, h1, l1;
        bf16split2(pa[i].x, pa[i].y, h0, l0);
        bf16split2(pa[i].z, pa[i].w, h1, l1);
        *(uint2*)(smg + G_AH + off) = make_uint2(h0, h1);
        *(uint2*)(smg + G_AL + off) = make_uint2(l0, l1);
        bf16split2(pb[i].x, pb[i].y, h0, l0);
        bf16split2(pb[i].z, pb[i].w, h1, l1);
        *(uint2*)(smg + G_BH + off) = make_uint2(h0, h1);
        *(uint2*)(smg + G_BL + off) = make_uint2(l0, l1);
    }
    __syncthreads();

    float d[2][8][4];
    #pragma unroll
    for (int mi = 0; mi < 2; ++mi)
        #pragma unroll
        for (int ni = 0; ni < 8; ++ni)
            #pragma unroll
            for (int q = 0; q < 4; ++q) d[mi][ni][q] = 0.0f;

    const int arow = wm * 32 + (lane & 15);
    const int akoff = (lane >> 4) << 3;
    const int brow = wn * 64 + (lane & 7);
    const int bkoff = ((lane >> 3) & 1) << 3;

    for (int kt = 0; kt < 32; ++kt) {
        if (kt < 31) {
            const float* Ap = Ag + (kt + 1) * 32;
            const float* Wp = Wg + (kt + 1) * 32;
            #pragma unroll
            for (int i = 0; i < 4; ++i) {
                pa[i] = *(const float4*)(Ap + (size_t)lr[i] * 1024 + lc[i]);
                pb[i] = *(const float4*)(Wp + (size_t)lr[i] * 1024 + lc[i]);
            }
        }
        const uint32_t st = sb + (kt & 1) * G_STAGE;
        #pragma unroll
        for (int kk = 0; kk < 32; kk += 16) {
            uint32_t ah[2][4], al[2][4], bh[8][2], bl[8][2];
            #pragma unroll
            for (int mi = 0; mi < 2; ++mi) {
                const uint32_t ao = st + (arow + mi * 16) * (G_LD * 2) + (kk + akoff) * 2;
                ldsm_x4(ah[mi], ao + G_AH);
                ldsm_x4(al[mi], ao + G_AL);
            }
            #pragma unroll
            for (int ni = 0; ni < 8; ++ni) {
                const uint32_t bo = st + (brow + ni * 8) * (G_LD * 2) + (kk + bkoff) * 2;
                ldsm_x2(bh[ni], bo + G_BH);
                ldsm_x2(bl[ni], bo + G_BL);
            }
            #pragma unroll
            for (int mi = 0; mi < 2; ++mi)
                #pragma unroll
                for (int ni = 0; ni < 8; ++ni) {
                    mma16816(d[mi][ni], ah[mi], bh[ni]);
                    mma16816(d[mi][ni], ah[mi], bl[ni]);
                    mma16816(d[mi][ni], al[mi], bh[ni]);
                }
        }
        if (kt < 31) {
            char* nb = smg + ((kt + 1) & 1) * G_STAGE;
            #pragma unroll
            for (int i = 0; i < 4; ++i) {
                const int off = lr[i] * (G_LD * 2) + lc[i] * 2;
                uint32_t h0, l0, h1, l1;
                bf16split2(pa[i].x, pa[i].y, h0, l0);
                bf16split2(pa[i].z, pa[i].w, h1, l1);
                *(uint2*)(nb + G_AH + off) = make_uint2(h0, h1);
                *(uint2*)(nb + G_AL + off) = make_uint2(l0, l1);
                bf16split2(pb[i].x, pb[i].y, h0, l0);
                bf16split2(pb[i].z, pb[i].w, h1, l1);
                *(uint2*)(nb + G_BH + off) = make_uint2(h0, h1);
                *(uint2*)(nb + G_BL + off) = make_uint2(l0, l1);
            }
        }
        __syncthreads();
    }

    // epilogue: c frag (row = +lane/4 [+8], col = +2*(lane%4) [+1])
    const int r_base = bm * 128 + wm * 32 + (lane >> 2);
    const int c_base = bn * 128 + wn * 64 + 2 * (lane & 3);
    #pragma unroll
    for (int mi = 0; mi < 2; ++mi)
        #pragma unroll
        for (int ni = 0; ni < 8; ++ni) {
            const int col = c_base + ni * 8;
            const float b0 = bias[col], b1 = bias[col + 1];
            #pragma unroll
            for (int rr = 0; rr < 2; ++rr) {
                const int row = r_base + mi * 16 + rr * 8;
                float2 v;
                v.x = d[mi][ni][rr * 2 + 0] + b0;
                v.y = d[mi][ni][rr * 2 + 1] + b1;
                if (SPLIT) {
                    const int bb = row >> 11;
                    const int s = row & (S_N - 1);
                    const int hh = col >> 6;
                    const int dk = col & 63;
                    *(float2*)(out + (((size_t)(bb * H_N + hh) * S_N + s) * DK_N) + dk) = v;
                } else {
                    *(float2*)(out + (size_t)row * D_N + col) = v;
                }
            }
        }
}

__global__ __launch_bounds__(256) void qkv_proj_mma(
    const float* __restrict__ q, const float* __restrict__ k, const float* __restrict__ v,
    const float* __restrict__ Wq, const float* __restrict__ Wk, const float* __restrict__ Wv,
    const float* __restrict__ bq, const float* __restrict__ bk, const float* __restrict__ bv,
    float* __restrict__ oq, float* __restrict__ ok, float* __restrict__ ov)
{
    const float* A; const float* W; const float* bias; float* out;
    if (blockIdx.z == 0)      { A = q; W = Wq; bias = bq; out = oq; }
    else if (blockIdx.z == 1) { A = k; W = Wk; bias = bk; out = ok; }
    else                      { A = v; W = Wv; bias = bv; out = ov; }
    gemm_mma_body<true>(A, W, bias, out, blockIdx.y, blockIdx.x);
}

__global__ __launch_bounds__(256) void oproj_mma(
    const float* __restrict__ A, const float* __restrict__ W,
    const float* __restrict__ bias, float* __restrict__ out)
{
    gemm_mma_body<false>(A, W, bias, out, blockIdx.y, blockIdx.x);
}

// ===========================================================================
// Flash attention on mma.sync (bf16 split, fp32 accum, online softmax)
// CTA: one (b,h) x 128 q-rows; 8 warps x 16 q-rows each; K-tile 128.
// smem: Qh|Ql (persistent), Kh|Kl|Vh|Vl (per tile), mask. stride 72 b16.
// ===========================================================================
#define F_LD 72                 // b16 stride (64 data + 8 pad)
#define F_T 18432               // 128*72*2 bytes
#define F_QH 0
#define F_QL 18432
#define F_KH 36864
#define F_KL 55296
#define F_VH 73728
#define F_VL 92160
#define F_MS 110592
#define SMEM_FLASH (110592 + 512)

__global__ __launch_bounds__(256)
void flash_mma(const float* __restrict__ Q, const float* __restrict__ K,
               const float* __restrict__ V, const int* __restrict__ mask,
               float* __restrict__ out)
{
    extern __shared__ char smf[];
    const uint32_t sb = smem_u32(smf);
    const int tid = threadIdx.x;
    const int lane = tid & 31;
    const int w = tid >> 5;
    const int bh = blockIdx.y;
    const int q0 = blockIdx.x * 128;
    const int b = bh >> 4;
    const int h = bh & 15;

    const float* Qg = Q + ((size_t)bh * S_N + q0) * DK_N;
    const float* Kg = K + (size_t)bh * S_N * DK_N;
    const float* Vg = V + (size_t)bh * S_N * DK_N;
    const int* mg = mask + b * S_N;

    // stage Q (scaled by 1/8) -> smem hi/lo
    #pragma unroll
    for (int i = 0; i < 8; ++i) {
        const int f = tid + i * 256;
        const int r = f >> 4;
        const int c4 = (f & 15) * 4;
        float4 v = *(const float4*)(Qg + (size_t)r * DK_N + c4);
        v.x *= 0.125f; v.y *= 0.125f; v.z *= 0.125f; v.w *= 0.125f;
        const int off = r * (F_LD * 2) + c4 * 2;
        uint32_t h0, l0, h1, l1;
        bf16split2(v.x, v.y, h0, l0);
        bf16split2(v.z, v.w, h1, l1);
        *(uint2*)(smf + F_QH + off) = make_uint2(h0, h1);
        *(uint2*)(smf + F_QL + off) = make_uint2(l0, l1);
    }
    __syncthreads();

    // Q fragments resident in registers (4 k-chunks of 16)
    uint32_t qh[4][4], ql[4][4];
    {
        const int row = w * 16 + (lane & 15);
        const int koff = (lane >> 4) << 3;
        #pragma unroll
        for (int kc = 0; kc < 4; ++kc) {
            const uint32_t ao = sb + row * (F_LD * 2) + (kc * 16 + koff) * 2;
            ldsm_x4(qh[kc], ao + F_QH);
            ldsm_x4(ql[kc], ao + F_QL);
        }
    }

    float o[8][4];
    #pragma unroll
    for (int vi = 0; vi < 8; ++vi)
        #pragma unroll
        for (int q = 0; q < 4; ++q) o[vi][q] = 0.0f;
    float mrow[2] = {-1e30f, -1e30f};
    float lrow[2] = {0.0f, 0.0f};

    const int brow = lane & 7;
    const int bsel = ((lane >> 3) & 1) << 3;
    const int vrow = (lane & 7) + bsel;
    const int c0 = 2 * (lane & 3);

    for (int kt = 0; kt < 16; ++kt) {
        __syncthreads();   // prior PV reads of V smem complete
        const float* Kt = Kg + (size_t)kt * 128 * DK_N;
        const float* Vt = Vg + (size_t)kt * 128 * DK_N;
        #pragma unroll
        for (int i = 0; i < 8; ++i) {
            const int f = tid + i * 256;
            const int r = f >> 4;
            const int c4 = (f & 15) * 4;
            const int off = r * (F_LD * 2) + c4 * 2;
            const float4 kv = *(const float4*)(Kt + (size_t)r * DK_N + c4);
            uint32_t h0, l0, h1, l1;
            bf16split2(kv.x, kv.y, h0, l0);
            bf16split2(kv.z, kv.w, h1, l1);
            *(uint2*)(smf + F_KH + off) = make_uint2(h0, h1);
            *(uint2*)(smf + F_KL + off) = make_uint2(l0, l1);
            const float4 vv = *(const float4*)(Vt + (size_t)r * DK_N + c4);
            bf16split2(vv.x, vv.y, h0, l0);
            bf16split2(vv.z, vv.w, h1, l1);
            *(uint2*)(smf + F_VH + off) = make_uint2(h0, h1);
            *(uint2*)(smf + F_VL + off) = make_uint2(l0, l1);
        }
        if (tid < 128) ((int*)(smf + F_MS))[tid] = mg[kt * 128 + tid];
        __syncthreads();

        // S = Qs @ K^T : 16 n-tiles of 8 keys
        float s[16][4];
        #pragma unroll
        for (int ni = 0; ni < 16; ++ni) {
            s[ni][0] = s[ni][1] = s[ni][2] = s[ni][3] = 0.0f;
            #pragma unroll
            for (int kc = 0; kc < 4; ++kc) {
                const uint32_t bo = sb + (ni * 8 + brow) * (F_LD * 2) + (kc * 16 + bsel) * 2;
                uint32_t bhh[2], bll[2];
                ldsm_x2(bhh, bo + F_KH);
                ldsm_x2(bll, bo + F_KL);
                mma16816(s[ni], qh[kc], bhh);
                mma16816(s[ni], qh[kc], bll);
                mma16816(s[ni], ql[kc], bhh);
            }
        }

        // mask (scores already scaled via Q)
        const int* msk = (const int*)(smf + F_MS);
        #pragma unroll
        for (int ni = 0; ni < 16; ++ni) {
            if (msk[ni * 8 + c0] == 0)     { s[ni][0] = -1e9f; s[ni][2] = -1e9f; }
            if (msk[ni * 8 + c0 + 1] == 0) { s[ni][1] = -1e9f; s[ni][3] = -1e9f; }
        }

        // online softmax (rows rr=0 -> regs 0,1 ; rr=1 -> regs 2,3)
        #pragma unroll
        for (int rr = 0; rr < 2; ++rr) {
            float mx = -1e30f;
            #pragma unroll
            for (int ni = 0; ni < 16; ++ni)
                mx = fmaxf(mx, fmaxf(s[ni][rr * 2], s[ni][rr * 2 + 1]));
            mx = fmaxf(mx, __shfl_xor_sync(0xffffffffu, mx, 1));
            mx = fmaxf(mx, __shfl_xor_sync(0xffffffffu, mx, 2));
            const float nm = fmaxf(mrow[rr], mx);
            const float corr = __expf(mrow[rr] - nm);
            float sum = 0.0f;
            #pragma unroll
            for (int ni = 0; ni < 16; ++ni) {
                const float p0 = __expf(s[ni][rr * 2]     - nm);
                const float p1 = __expf(s[ni][rr * 2 + 1] - nm);
                s[ni][rr * 2] = p0; s[ni][rr * 2 + 1] = p1;
                sum += p0 + p1;
            }
            sum += __shfl_xor_sync(0xffffffffu, sum, 1);
            sum += __shfl_xor_sync(0xffffffffu, sum, 2);
            lrow[rr] = lrow[rr] * corr + sum;
            mrow[rr] = nm;
            #pragma unroll
            for (int vi = 0; vi < 8; ++vi) {
                o[vi][rr * 2]     *= corr;
                o[vi][rr * 2 + 1] *= corr;
            }
        }

        // O += P @ V (P: accumulator frags -> A frags; V via ldmatrix.trans)
        #pragma unroll
        for (int kc = 0; kc < 8; ++kc) {
            uint32_t ah4[4], al4[4];
            bf16split2(s[2 * kc][0],     s[2 * kc][1],     ah4[0], al4[0]);
            bf16split2(s[2 * kc][2],     s[2 * kc][3],     ah4[1], al4[1]);
            bf16split2(s[2 * kc + 1][0], s[2 * kc + 1][1], ah4[2], al4[2]);
            bf16split2(s[2 * kc + 1][2], s[2 * kc + 1][3], ah4[3], al4[3]);
            #pragma unroll
            for (int vi = 0; vi < 8; ++vi) {
                const uint32_t vo = sb + (kc * 16 + vrow) * (F_LD * 2) + vi * 16;
                uint32_t bhh[2], bll[2];
                ldsm_x2t(bhh, vo + F_VH);
                ldsm_x2t(bll, vo + F_VL);
                mma16816(o[vi], ah4, bhh);
                mma16816(o[vi], ah4, bll);
                mma16816(o[vi], al4, bhh);
            }
        }
    }

    // epilogue -> ctx flat [b*S+s][D] at col h*64+dk
    const float inv0 = 1.0f / lrow[0];
    const float inv1 = 1.0f / lrow[1];
    const int r0 = q0 + w * 16 + (lane >> 2);
    #pragma unroll
    for (int vi = 0; vi < 8; ++vi) {
        const int dk = vi * 8 + c0;
        float2 v0, v1;
        v0.x = o[vi][0] * inv0; v0.y = o[vi][1] * inv0;
        v1.x = o[vi][2] * inv1; v1.y = o[vi][3] * inv1;
        *(float2*)(out + ((size_t)b * S_N + r0) * D_N + h * DK_N + dk) = v0;
        *(float2*)(out + ((size_t)b * S_N + r0 + 8) * D_N + h * DK_N + dk) = v1;
    }
}

// ---------------------------------------------------------------------------
extern "C" void kernel_launch(void* const* d_in, const int* in_sizes, int n_in,
                              void* d_out, int out_size)
{
    (void)in_sizes; (void)n_in; (void)out_size;
    const float* query = (const float*)d_in[0];
    const float* key   = (const float*)d_in[1];
    const float* value = (const float*)d_in[2];
    const int*   mask  = (const int*)d_in[3];
    const float* Wq = (const float*)d_in[4];
    const float* bq = (const float*)d_in[5];
    const float* Wk = (const float*)d_in[6];
    const float* bk = (const float*)d_in[7];
    const float* Wv = (const float*)d_in[8];
    const float* bv = (const float*)d_in[9];
    const float* Wo = (const float*)d_in[10];
    const float* bo = (const float*)d_in[11];
    float* out = (float*)d_out;

    void *pQ, *pK, *pV, *pC;
    cudaGetSymbolAddress(&pQ, g_Q);
    cudaGetSymbolAddress(&pK, g_K);
    cudaGetSymbolAddress(&pV, g_V);
    cudaGetSymbolAddress(&pC, g_C);

    cudaFuncSetAttribute(qkv_proj_mma, cudaFuncAttributeMaxDynamicSharedMemorySize, SMEM_GEMM);
    cudaFuncSetAttribute(oproj_mma,    cudaFuncAttributeMaxDynamicSharedMemorySize, SMEM_GEMM);
    cudaFuncSetAttribute(flash_mma,    cudaFuncAttributeMaxDynamicSharedMemorySize, SMEM_FLASH);

    qkv_proj_mma<<<dim3(8, 64, 3), 256, SMEM_GEMM>>>(
        query, key, value, Wq, Wk, Wv, bq, bk, bv,
        (float*)pQ, (float*)pK, (float*)pV);

    flash_mma<<<dim3(S_N / 128, B_N * H_N), 256, SMEM_FLASH>>>(
        (const float*)pQ, (const float*)pK, (const float*)pV, mask, (float*)pC);

    oproj_mma<<<dim3(8, 64), 256, SMEM_GEMM>>>((const float*)pC, Wo, bo, out);
}

// round 6
// speedup vs baseline: 2.7184x; 1.0100x over previous
#include <cuda_runtime.h>
#include <cuda_bf16.h>
#include <stdint.h>

// Problem constants
#define B_N 4
#define S_N 2048
#define D_N 1024
#define H_N 16
#define DK_N 64

#define IN_EL   (3u * 8192u * 1024u)   // q,k,v inputs stacked
#define W_EL    (4u * 1024u * 1024u)   // Wq,Wk,Wv,Wo stacked
#define HEAD_EL (8192u * 1024u)        // B*H*S*DK == M*D

// bf16 hi/lo scratch (allocation-free: static device globals)
__device__ __nv_bfloat16 g_inh[IN_EL], g_inl[IN_EL];
__device__ __nv_bfloat16 g_wh[W_EL],  g_wl[W_EL];
__device__ __nv_bfloat16 g_qh[HEAD_EL], g_ql[HEAD_EL];
__device__ __nv_bfloat16 g_kh[HEAD_EL], g_kl[HEAD_EL];
__device__ __nv_bfloat16 g_vh[HEAD_EL], g_vl[HEAD_EL];
__device__ __nv_bfloat16 g_ch[HEAD_EL], g_cl[HEAD_EL];

// ===========================================================================
// Portable helpers (compute_103-safe: ldmatrix / mma.sync / cp.async only)
// ===========================================================================
__device__ __forceinline__ uint32_t smem_u32(const void* p) {
    uint32_t a;
    asm("{ .reg .u64 t; cvta.to.shared.u64 t, %1; cvt.u32.u64 %0, t; }"
        : "=r"(a) : "l"(p));
    return a;
}

__device__ __forceinline__ void ldsm_x4(uint32_t* r, uint32_t addr) {
    asm volatile("ldmatrix.sync.aligned.m8n8.x4.shared.b16 {%0,%1,%2,%3}, [%4];"
        : "=r"(r[0]), "=r"(r[1]), "=r"(r[2]), "=r"(r[3]) : "r"(addr));
}
__device__ __forceinline__ void ldsm_x2(uint32_t* r, uint32_t addr) {
    asm volatile("ldmatrix.sync.aligned.m8n8.x2.shared.b16 {%0,%1}, [%2];"
        : "=r"(r[0]), "=r"(r[1]) : "r"(addr));
}
__device__ __forceinline__ void ldsm_x2t(uint32_t* r, uint32_t addr) {
    asm volatile("ldmatrix.sync.aligned.m8n8.x2.trans.shared.b16 {%0,%1}, [%2];"
        : "=r"(r[0]), "=r"(r[1]) : "r"(addr));
}

__device__ __forceinline__ void mma16816(float* d, const uint32_t* a, const uint32_t* b) {
    asm volatile(
        "mma.sync.aligned.m16n8k16.row.col.f32.bf16.bf16.f32 "
        "{%0,%1,%2,%3}, {%4,%5,%6,%7}, {%8,%9}, {%0,%1,%2,%3};"
        : "+f"(d[0]), "+f"(d[1]), "+f"(d[2]), "+f"(d[3])
        : "r"(a[0]), "r"(a[1]), "r"(a[2]), "r"(a[3]), "r"(b[0]), "r"(b[1]));
}

__device__ __forceinline__ void bf16split2(float x, float y, uint32_t& hi, uint32_t& lo) {
    union { __nv_bfloat162 b; uint32_t u; } h, l;
    h.b = __floats2bfloat162_rn(x, y);
    l.b = __floats2bfloat162_rn(x - __low2float(h.b), y - __high2float(h.b));
    hi = h.u; lo = l.u;
}

__device__ __forceinline__ void cpa16(uint32_t s, const void* g) {
    asm volatile("cp.async.cg.shared.global [%0], [%1], 16;" :: "r"(s), "l"(g));
}
#define CP_COMMIT() asm volatile("cp.async.commit_group;" ::: "memory")
#define CP_WAIT(n)  asm volatile("cp.async.wait_group %0;" :: "n"(n) : "memory")

// ===========================================================================
// Pre-pass: fp32 -> bf16 hi/lo split arrays (4 floats / thread)
// ===========================================================================
__global__ __launch_bounds__(256) void convert_split(
    const float* __restrict__ src, __nv_bfloat16* __restrict__ dh,
    __nv_bfloat16* __restrict__ dl, int n4)
{
    const int i = blockIdx.x * 256 + threadIdx.x;
    if (i < n4) {
        const float4 v = ((const float4*)src)[i];
        uint32_t h0, l0, h1, l1;
        bf16split2(v.x, v.y, h0, l0);
        bf16split2(v.z, v.w, h1, l1);
        ((uint2*)dh)[i] = make_uint2(h0, h1);
        ((uint2*)dl)[i] = make_uint2(l0, l1);
    }
}

// ===========================================================================
// GEMM on mma.sync: D = A @ W^T (+bias). A,W given as bf16 hi/lo arrays.
// CTA 128x128, BK=32, 256 thr (8 warps: 4m x 2n), cp.async 2-stage pipeline.
// smem/stage: Ah|Al|Bh|Bl, each 128 x 40(b16 pad stride) = 10240 B.
// MODE 0: fp32 out flat [row,D] + bias.
// MODE 1: bf16 hi/lo out, head layout [(b*H+h)*S+s]*64+dk, (d+bias)*scale.
// ===========================================================================
#define G_STAGE 40960
#define SMEM_GEMM (2 * G_STAGE)

__device__ __forceinline__ void gemm_stage_issue(
    uint32_t st, const __nv_bfloat16* __restrict__ a0,
    const __nv_bfloat16* __restrict__ a1, const __nv_bfloat16* __restrict__ a2,
    const __nv_bfloat16* __restrict__ a3, int kt, int tid)
{
    #pragma unroll
    for (int i = 0; i < 8; ++i) {
        const int comp = i >> 1;                 // compile-time per i
        const int c = tid + (i & 1) * 256;       // 0..511
        const int row = c >> 2;
        const int ch = c & 3;
        const uint32_t dst = st + comp * 10240 + row * 80 + ch * 16;
        const __nv_bfloat16* src =
            (comp == 0 ? a0 : comp == 1 ? a1 : comp == 2 ? a2 : a3)
            + (size_t)row * 1024 + kt * 32 + ch * 8;
        cpa16(dst, src);
    }
}

template <int MODE>
__device__ __forceinline__ void gemm_bf_body(
    const __nv_bfloat16* __restrict__ Ah, const __nv_bfloat16* __restrict__ Al,
    const __nv_bfloat16* __restrict__ Wh, const __nv_bfloat16* __restrict__ Wl,
    const float* __restrict__ bias, float scale,
    float* __restrict__ outf,
    __nv_bfloat16* __restrict__ outh, __nv_bfloat16* __restrict__ outl,
    int bm, int bn)
{
    extern __shared__ char smg[];
    const uint32_t sb = smem_u32(smg);
    const int tid = threadIdx.x;
    const int lane = tid & 31;
    const int w = tid >> 5;
    const int wm = w & 3;
    const int wn = w >> 2;

    const __nv_bfloat16* Agh = Ah + (size_t)bm * 128 * 1024;
    const __nv_bfloat16* Agl = Al + (size_t)bm * 128 * 1024;
    const __nv_bfloat16* Wgh = Wh + (size_t)bn * 128 * 1024;
    const __nv_bfloat16* Wgl = Wl + (size_t)bn * 128 * 1024;

    gemm_stage_issue(sb,           Agh, Agl, Wgh, Wgl, 0, tid); CP_COMMIT();
    gemm_stage_issue(sb + G_STAGE, Agh, Agl, Wgh, Wgl, 1, tid); CP_COMMIT();

    float d[2][8][4];
    #pragma unroll
    for (int mi = 0; mi < 2; ++mi)
        #pragma unroll
        for (int ni = 0; ni < 8; ++ni)
            #pragma unroll
            for (int q = 0; q < 4; ++q) d[mi][ni][q] = 0.0f;

    const int arow = wm * 32 + (lane & 15);
    const int akoff = (lane >> 4) << 3;
    const int brow = wn * 64 + (lane & 7);
    const int bkoff = ((lane >> 3) & 1) << 3;

    for (int kt = 0; kt < 32; ++kt) {
        if (kt >= 30) { CP_WAIT(0); } else { CP_WAIT(1); }
        __syncthreads();
        const uint32_t st = sb + (kt & 1) * G_STAGE;
        #pragma unroll
        for (int kk = 0; kk < 32; kk += 16) {
            uint32_t ah[2][4], al[2][4];
            #pragma unroll
            for (int mi = 0; mi < 2; ++mi) {
                const uint32_t ao = st + (arow + mi * 16) * 80 + (kk + akoff) * 2;
                ldsm_x4(ah[mi], ao);
                ldsm_x4(al[mi], ao + 10240);
            }
            #pragma unroll
            for (int ni = 0; ni < 8; ++ni) {
                uint32_t bh[2], bl[2];
                const uint32_t bo = st + 20480 + (brow + ni * 8) * 80 + (kk + bkoff) * 2;
                ldsm_x2(bh, bo);
                ldsm_x2(bl, bo + 10240);
                #pragma unroll
                for (int mi = 0; mi < 2; ++mi) {
                    mma16816(d[mi][ni], ah[mi], bh);
                    mma16816(d[mi][ni], ah[mi], bl);
                    mma16816(d[mi][ni], al[mi], bh);
                }
            }
        }
        __syncthreads();
        if (kt + 2 < 32) {
            gemm_stage_issue(sb + (kt & 1) * G_STAGE, Agh, Agl, Wgh, Wgl, kt + 2, tid);
            CP_COMMIT();
        }
    }

    // epilogue: c frag rows = r_base + mi*16 + rr*8, cols = c_base + ni*8 (+1)
    const int r_base = bm * 128 + wm * 32 + (lane >> 2);
    const int c_base = bn * 128 + wn * 64 + 2 * (lane & 3);
    #pragma unroll
    for (int mi = 0; mi < 2; ++mi)
        #pragma unroll
        for (int ni = 0; ni < 8; ++ni) {
            const int col = c_base + ni * 8;
            const float b0 = bias[col], b1 = bias[col + 1];
            #pragma unroll
            for (int rr = 0; rr < 2; ++rr) {
                const int row = r_base + mi * 16 + rr * 8;
                const float vx = (d[mi][ni][rr * 2 + 0] + b0) * scale;
                const float vy = (d[mi][ni][rr * 2 + 1] + b1) * scale;
                if (MODE == 1) {
                    const int bb = row >> 11;
                    const int s = row & (S_N - 1);
                    const int hh = col >> 6;
                    const int dk = col & 63;
                    const size_t idx = (((size_t)(bb * H_N + hh) * S_N + s) * DK_N) + dk;
                    uint32_t h, l;
                    bf16split2(vx, vy, h, l);
                    *(uint32_t*)(outh + idx) = h;
                    *(uint32_t*)(outl + idx) = l;
                } else {
                    float2 v; v.x = vx; v.y = vy;
                    *(float2*)(outf + (size_t)row * D_N + col) = v;
                }
            }
        }
}

__global__ __launch_bounds__(256, 2) void qkv_proj_mma(
    const float* __restrict__ bq, const float* __restrict__ bk,
    const float* __restrict__ bv)
{
    const int z = blockIdx.z;
    const float* bias = (z == 0) ? bq : (z == 1) ? bk : bv;
    __nv_bfloat16* oh = (z == 0) ? g_qh : (z == 1) ? g_kh : g_vh;
    __nv_bfloat16* ol = (z == 0) ? g_ql : (z == 1) ? g_kl : g_vl;
    const float scale = (z == 0) ? 0.125f : 1.0f;
    gemm_bf_body<1>(g_inh + (size_t)z * HEAD_EL, g_inl + (size_t)z * HEAD_EL,
                    g_wh + (size_t)z * 1024 * 1024, g_wl + (size_t)z * 1024 * 1024,
                    bias, scale, nullptr, oh, ol, blockIdx.y, blockIdx.x);
}

__global__ __launch_bounds__(256, 2) void oproj_mma(
    const float* __restrict__ bo, float* __restrict__ out)
{
    gemm_bf_body<0>(g_ch, g_cl,
                    g_wh + (size_t)3 * 1024 * 1024, g_wl + (size_t)3 * 1024 * 1024,
                    bo, 1.0f, out, nullptr, nullptr, blockIdx.y, blockIdx.x);
}

// ===========================================================================
// Flash attention on mma.sync, all-bf16 inputs, cp.async 2-stage K/V pipeline.
// CTA: one (b,h) x 128 q-rows; 8 warps x 16 q-rows; K-tile 128.
// smem: Qh|Ql (persistent) | 2 stages of (Kh|Kl|Vh|Vl) | mask[2048].
// stride 72 b16 = 144 B per row.
// ===========================================================================
#define FQ_H 0
#define FQ_L 18432
#define F_KV0 36864
#define F_KVSTAGE 73728          // 4 components x 18432
#define F_MS (F_KV0 + 2 * F_KVSTAGE)   // 184320
#define SMEM_FLASH (F_MS + 8192)       // 192512

__device__ __forceinline__ void kv_stage_issue(
    uint32_t st, const __nv_bfloat16* __restrict__ kh,
    const __nv_bfloat16* __restrict__ kl, const __nv_bfloat16* __restrict__ vh,
    const __nv_bfloat16* __restrict__ vl, int kt, int tid)
{
    #pragma unroll
    for (int i = 0; i < 16; ++i) {
        const int comp = i >> 2;
        const int c = tid + (i & 3) * 256;   // 0..1023
        const int row = c >> 3;
        const int ch = c & 7;
        const uint32_t dst = st + comp * 18432 + row * 144 + ch * 16;
        const __nv_bfloat16* src =
            (comp == 0 ? kh : comp == 1 ? kl : comp == 2 ? vh : vl)
            + ((size_t)kt * 128 + row) * 64 + ch * 8;
        cpa16(dst, src);
    }
}

__global__ __launch_bounds__(256)
void flash_mma(const int* __restrict__ mask, float* /*unused*/)
{
    extern __shared__ char smf[];
    const uint32_t sb = smem_u32(smf);
    const int tid = threadIdx.x;
    const int lane = tid & 31;
    const int w = tid >> 5;
    const int bh = blockIdx.y;
    const int q0 = blockIdx.x * 128;
    const int b = bh >> 4;
    const int h = bh & 15;

    const size_t hoff = (size_t)bh * S_N * DK_N;
    const __nv_bfloat16* Qh = g_qh + hoff + (size_t)q0 * DK_N;
    const __nv_bfloat16* Ql = g_ql + hoff + (size_t)q0 * DK_N;
    const __nv_bfloat16* Kh = g_kh + hoff;
    const __nv_bfloat16* Kl = g_kl + hoff;
    const __nv_bfloat16* Vh = g_vh + hoff;
    const __nv_bfloat16* Vl = g_vl + hoff;
    const int* mg = mask + b * S_N;

    // prologue: Q + mask + KV stage0 (group0), KV stage1 (group1)
    #pragma unroll
    for (int i = 0; i < 8; ++i) {
        const int comp = i >> 2;
        const int c = tid + (i & 3) * 256;
        const int row = c >> 3;
        const int ch = c & 7;
        const uint32_t dst = sb + comp * 18432 + row * 144 + ch * 16;
        const __nv_bfloat16* src = (comp == 0 ? Qh : Ql) + (size_t)row * 64 + ch * 8;
        cpa16(dst, src);
    }
    #pragma unroll
    for (int i = 0; i < 2; ++i) {
        const int c = tid + i * 256;         // 0..511 chunks of 16B (mask 8192B)
        cpa16(sb + F_MS + c * 16, mg + c * 4);
    }
    kv_stage_issue(sb + F_KV0, Kh, Kl, Vh, Vl, 0, tid);
    CP_COMMIT();
    kv_stage_issue(sb + F_KV0 + F_KVSTAGE, Kh, Kl, Vh, Vl, 1, tid);
    CP_COMMIT();

    uint32_t qh[4][4], ql[4][4];

    float o[8][4];
    #pragma unroll
    for (int vi = 0; vi < 8; ++vi)
        #pragma unroll
        for (int q = 0; q < 4; ++q) o[vi][q] = 0.0f;
    float mrow[2] = {-1e30f, -1e30f};
    float lrow[2] = {0.0f, 0.0f};

    const int brow = lane & 7;
    const int bsel = ((lane >> 3) & 1) << 3;
    const int vrow = (lane & 7) + bsel;
    const int c0 = 2 * (lane & 3);
    const int* msk = (const int*)(smf + F_MS);

    for (int kt = 0; kt < 16; ++kt) {
        if (kt >= 14) { CP_WAIT(0); } else { CP_WAIT(1); }
        __syncthreads();
        const uint32_t st = sb + F_KV0 + (kt & 1) * F_KVSTAGE;

        if (kt == 0) {  // Q fragments resident (group0 complete)
            const int row = w * 16 + (lane & 15);
            const int koff = (lane >> 4) << 3;
            #pragma unroll
            for (int kc = 0; kc < 4; ++kc) {
                const uint32_t ao = sb + row * 144 + (kc * 16 + koff) * 2;
                ldsm_x4(qh[kc], ao + FQ_H);
                ldsm_x4(ql[kc], ao + FQ_L);
            }
        }

        // S = Qs @ K^T : 16 n-tiles of 8 keys
        float s[16][4];
        #pragma unroll
        for (int ni = 0; ni < 16; ++ni) {
            s[ni][0] = s[ni][1] = s[ni][2] = s[ni][3] = 0.0f;
            #pragma unroll
            for (int kc = 0; kc < 4; ++kc) {
                const uint32_t bo = st + (ni * 8 + brow) * 144 + (kc * 16 + bsel) * 2;
                uint32_t bhh[2], bll[2];
                ldsm_x2(bhh, bo);
                ldsm_x2(bll, bo + 18432);
                mma16816(s[ni], qh[kc], bhh);
                mma16816(s[ni], qh[kc], bll);
                mma16816(s[ni], ql[kc], bhh);
            }
        }

        // mask
        #pragma unroll
        for (int ni = 0; ni < 16; ++ni) {
            if (msk[kt * 128 + ni * 8 + c0] == 0)     { s[ni][0] = -1e9f; s[ni][2] = -1e9f; }
            if (msk[kt * 128 + ni * 8 + c0 + 1] == 0) { s[ni][1] = -1e9f; s[ni][3] = -1e9f; }
        }

        // online softmax
        #pragma unroll
        for (int rr = 0; rr < 2; ++rr) {
            float mx = -1e30f;
            #pragma unroll
            for (int ni = 0; ni < 16; ++ni)
                mx = fmaxf(mx, fmaxf(s[ni][rr * 2], s[ni][rr * 2 + 1]));
            mx = fmaxf(mx, __shfl_xor_sync(0xffffffffu, mx, 1));
            mx = fmaxf(mx, __shfl_xor_sync(0xffffffffu, mx, 2));
            const float nm = fmaxf(mrow[rr], mx);
            const float corr = __expf(mrow[rr] - nm);
            float sum = 0.0f;
            #pragma unroll
            for (int ni = 0; ni < 16; ++ni) {
                const float p0 = __expf(s[ni][rr * 2]     - nm);
                const float p1 = __expf(s[ni][rr * 2 + 1] - nm);
                s[ni][rr * 2] = p0; s[ni][rr * 2 + 1] = p1;
                sum += p0 + p1;
            }
            sum += __shfl_xor_sync(0xffffffffu, sum, 1);
            sum += __shfl_xor_sync(0xffffffffu, sum, 2);
            lrow[rr] = lrow[rr] * corr + sum;
            mrow[rr] = nm;
            #pragma unroll
            for (int vi = 0; vi < 8; ++vi) {
                o[vi][rr * 2]     *= corr;
                o[vi][rr * 2 + 1] *= corr;
            }
        }

        // O += P @ V (P accumulator frags -> A frags; V via ldmatrix.trans)
        #pragma unroll
        for (int kc = 0; kc < 8; ++kc) {
            uint32_t ah4[4], al4[4];
            bf16split2(s[2 * kc][0],     s[2 * kc][1],     ah4[0], al4[0]);
            bf16split2(s[2 * kc][2],     s[2 * kc][3],     ah4[1], al4[1]);
            bf16split2(s[2 * kc + 1][0], s[2 * kc + 1][1], ah4[2], al4[2]);
            bf16split2(s[2 * kc + 1][2], s[2 * kc + 1][3], ah4[3], al4[3]);
            #pragma unroll
            for (int vi = 0; vi < 8; ++vi) {
                const uint32_t vo = st + 36864 + (kc * 16 + vrow) * 144 + vi * 16;
                uint32_t bhh[2], bll[2];
                ldsm_x2t(bhh, vo);
                ldsm_x2t(bll, vo + 18432);
                mma16816(o[vi], ah4, bhh);
                mma16816(o[vi], ah4, bll);
                mma16816(o[vi], al4, bhh);
            }
        }

        __syncthreads();
        if (kt + 2 < 16) {
            kv_stage_issue(sb + F_KV0 + (kt & 1) * F_KVSTAGE, Kh, Kl, Vh, Vl, kt + 2, tid);
            CP_COMMIT();
        }
    }

    // epilogue: ctx as bf16 hi/lo, flat [b*S+s][D] at col h*64+dk
    const float inv0 = 1.0f / lrow[0];
    const float inv1 = 1.0f / lrow[1];
    const int r0 = q0 + w * 16 + (lane >> 2);
    const size_t base0 = ((size_t)b * S_N + r0) * D_N + h * DK_N;
    const size_t base1 = base0 + 8 * D_N;
    #pragma unroll
    for (int vi = 0; vi < 8; ++vi) {
        const int dk = vi * 8 + c0;
        uint32_t h0, l0, h1, l1;
        bf16split2(o[vi][0] * inv0, o[vi][1] * inv0, h0, l0);
        bf16split2(o[vi][2] * inv1, o[vi][3] * inv1, h1, l1);
        *(uint32_t*)(g_ch + base0 + dk) = h0;
        *(uint32_t*)(g_cl + base0 + dk) = l0;
        *(uint32_t*)(g_ch + base1 + dk) = h1;
        *(uint32_t*)(g_cl + base1 + dk) = l1;
    }
}

// ---------------------------------------------------------------------------
extern "C" void kernel_launch(void* const* d_in, const int* in_sizes, int n_in,
                              void* d_out, int out_size)
{
    (void)in_sizes; (void)n_in; (void)out_size;
    const float* query = (const float*)d_in[0];
    const float* key   = (const float*)d_in[1];
    const float* value = (const float*)d_in[2];
    const int*   mask  = (const int*)d_in[3];
    const float* Wq = (const float*)d_in[4];
    const float* bq = (const float*)d_in[5];
    const float* Wk = (const float*)d_in[6];
    const float* bk = (const float*)d_in[7];
    const float* Wv = (const float*)d_in[8];
    const float* bv = (const float*)d_in[9];
    const float* Wo = (const float*)d_in[10];
    const float* bo = (const float*)d_in[11];
    float* out = (float*)d_out;

    void *pih, *pil, *pwh, *pwl;
    cudaGetSymbolAddress(&pih, g_inh);
    cudaGetSymbolAddress(&pil, g_inl);
    cudaGetSymbolAddress(&pwh, g_wh);
    cudaGetSymbolAddress(&pwl, g_wl);
    __nv_bfloat16* inh = (__nv_bfloat16*)pih;
    __nv_bfloat16* inl = (__nv_bfloat16*)pil;
    __nv_bfloat16* wh  = (__nv_bfloat16*)pwh;
    __nv_bfloat16* wl  = (__nv_bfloat16*)pwl;

    cudaFuncSetAttribute(qkv_proj_mma, cudaFuncAttributeMaxDynamicSharedMemorySize, SMEM_GEMM);
    cudaFuncSetAttribute(oproj_mma,    cudaFuncAttributeMaxDynamicSharedMemorySize, SMEM_GEMM);
    cudaFuncSetAttribute(flash_mma,    cudaFuncAttributeMaxDynamicSharedMemorySize, SMEM_FLASH);

    // pre-pass conversions: inputs (8.4M el each) + weights (1M el each)
    const int n4_in = (int)(HEAD_EL / 4);
    const int n4_w  = 1024 * 1024 / 4;
    convert_split<<<n4_in / 256, 256>>>(query, inh,                inl,                n4_in);
    convert_split<<<n4_in / 256, 256>>>(key,   inh + HEAD_EL,      inl + HEAD_EL,      n4_in);
    convert_split<<<n4_in / 256, 256>>>(value, inh + 2u * HEAD_EL, inl + 2u * HEAD_EL, n4_in);
    convert_split<<<n4_w / 256, 256>>>(Wq, wh,                 wl,                 n4_w);
    convert_split<<<n4_w / 256, 256>>>(Wk, wh + 1024 * 1024,   wl + 1024 * 1024,   n4_w);
    convert_split<<<n4_w / 256, 256>>>(Wv, wh + 2u * 1024 * 1024, wl + 2u * 1024 * 1024, n4_w);
    convert_split<<<n4_w / 256, 256>>>(Wo, wh + 3u * 1024 * 1024, wl + 3u * 1024 * 1024, n4_w);

    qkv_proj_mma<<<dim3(8, 64, 3), 256, SMEM_GEMM>>>(bq, bk, bv);

    flash_mma<<<dim3(S_N / 128, B_N * H_N), 256, SMEM_FLASH>>>(mask, nullptr);

    oproj_mma<<<dim3(8, 64), 256, SMEM_GEMM>>>(bo, out);
}